// round 3
// baseline (speedup 1.0000x reference)
#include <cuda_runtime.h>
#include <cstdint>
#include <cstddef>

#define EPSV  1e-5f
#define NROWS 16384
#define HID   4096

// ---------------------------------------------------------------------------
// Device scratch (no allocation allowed)
// ---------------------------------------------------------------------------
__device__ __align__(16) unsigned char g_xb  [NROWS * 768];           // s8 ±1 input
__device__ __align__(16) unsigned char g_act0[(size_t)NROWS * HID];   // s8 ±1 acts ping
__device__ __align__(16) unsigned char g_act1[(size_t)NROWS * HID];   // s8 ±1 acts pong
__device__ __align__(16) unsigned char g_w1  [HID * 768];
__device__ __align__(16) unsigned char g_w2  [(size_t)HID * HID];
__device__ __align__(16) unsigned char g_w3  [(size_t)HID * HID];
__device__ __align__(16) unsigned char g_w4  [16 * HID];
__device__ float4 g_par[3 * HID];                                     // {bias, mean, scale, beta}

// ---------------------------------------------------------------------------
// PTX helpers — all plain-target (no sm_103a-only instructions!)
// ---------------------------------------------------------------------------
__device__ __forceinline__ uint32_t smem_u32(const void* p) {
    uint32_t a;
    asm("{ .reg .u64 t; cvta.to.shared.u64 t, %1; cvt.u32.u64 %0, t; }" : "=r"(a) : "l"(p));
    return a;
}
__device__ __forceinline__ void cp_async16(uint32_t dst, const void* src) {
    asm volatile("cp.async.cg.shared.global [%0], [%1], 16;" :: "r"(dst), "l"(src) : "memory");
}
__device__ __forceinline__ void ldsm_x4(uint32_t (&r)[4], uint32_t addr) {
    asm volatile("ldmatrix.sync.aligned.m8n8.x4.shared.b16 {%0,%1,%2,%3}, [%4];"
                 : "=r"(r[0]), "=r"(r[1]), "=r"(r[2]), "=r"(r[3]) : "r"(addr));
}
__device__ __forceinline__ void mma_s8(uint32_t (&d)[4], const uint32_t (&a)[4],
                                       uint32_t b0, uint32_t b1) {
    asm volatile(
        "mma.sync.aligned.m16n8k32.row.col.s32.s8.s8.s32 "
        "{%0,%1,%2,%3}, {%4,%5,%6,%7}, {%8,%9}, {%0,%1,%2,%3};"
        : "+r"(d[0]), "+r"(d[1]), "+r"(d[2]), "+r"(d[3])
        : "r"(a[0]), "r"(a[1]), "r"(a[2]), "r"(a[3]), "r"(b0), "r"(b1));
}

// ---------------------------------------------------------------------------
// sign conversion: byte = (x<0) ? 0xFF (-1 s8) : 0x01 (+1 s8)
// ---------------------------------------------------------------------------
__global__ void cvt_sign(const float* __restrict__ src, unsigned char* __restrict__ dst, int n4) {
    int i = blockIdx.x * blockDim.x + threadIdx.x;
    if (i >= n4) return;
    float4 v = ((const float4*)src)[i];
    uchar4 o;
    o.x = (v.x < 0.f) ? 0xFF : 0x01;
    o.y = (v.y < 0.f) ? 0xFF : 0x01;
    o.z = (v.z < 0.f) ? 0xFF : 0x01;
    o.w = (v.w < 0.f) ? 0xFF : 0x01;
    ((uchar4*)dst)[i] = o;
}
__global__ void cvt_sign_x(const float* __restrict__ src, unsigned char* __restrict__ dst) {
    int i = blockIdx.x * blockDim.x + threadIdx.x;   // NROWS*192 float4 units
    int row = i / 192, q = i - row * 192;
    if (row >= NROWS) return;
    float4 v = *(const float4*)(src + (size_t)row * 784 + q * 4);
    uchar4 o;
    o.x = (v.x < 0.f) ? 0xFF : 0x01;
    o.y = (v.y < 0.f) ? 0xFF : 0x01;
    o.z = (v.z < 0.f) ? 0xFF : 0x01;
    o.w = (v.w < 0.f) ? 0xFF : 0x01;
    *(uchar4*)(dst + (size_t)row * 768 + q * 4) = o;
}
__global__ void prep_par(const float* __restrict__ b, const float* __restrict__ g,
                         const float* __restrict__ be, const float* __restrict__ m,
                         const float* __restrict__ v, float4* __restrict__ par, int n) {
    int i = blockIdx.x * blockDim.x + threadIdx.x;
    if (i >= n) return;
    float sc = __fmul_rn(g[i], rsqrtf(__fadd_rn(v[i], EPSV)));
    par[i] = make_float4(b[i], m[i], sc, be[i]);
}

// ---------------------------------------------------------------------------
// int8 IMMA GEMM + BN threshold + ±1 s8 repack.
// CTA 128x128, BK=64, 256 threads (4x2 warps, warp tile 32x64).
// Smem rows padded to 80B -> LDSM.x4 conflict-free, no swizzle needed.
// ---------------------------------------------------------------------------
#define RSTR  80
#define STAGE (128 * RSTR)          // 10240 B per operand per stage

__global__ void __launch_bounds__(256) imma_kernel(
        const unsigned char* __restrict__ A, const unsigned char* __restrict__ W,
        const float4* __restrict__ par, unsigned char* __restrict__ Out, int K) {
    __shared__ __align__(128) unsigned char smem[4 * STAGE];   // 40 KB: 2 stages x (A,B)
    const uint32_t sb = smem_u32(smem);
    const int tid  = threadIdx.x;
    const int lane = tid & 31, wid = tid >> 5;
    const int warpM = wid & 3, warpN = wid >> 2;          // 4 x 2 warp grid
    const int rowBase = blockIdx.y << 7, colBase = blockIdx.x << 7;

    // ldmatrix per-thread row assignment (x4: matrix j = lane>>3)
    const int j  = lane >> 3, r8 = lane & 7;
    const int jr = ((j & 1) << 3) + r8;                   // row within 16-row tile
    const uint32_t khalf = (uint32_t)((j >> 1) << 4);     // 0 or 16 bytes

    uint32_t aBase[2], bBase[4];
#pragma unroll
    for (int m = 0; m < 2; ++m)
        aBase[m] = sb + (uint32_t)(warpM * 32 + m * 16 + jr) * RSTR + khalf;
#pragma unroll
    for (int p = 0; p < 4; ++p)
        bBase[p] = sb + 2 * STAGE + (uint32_t)(warpN * 64 + p * 16 + jr) * RSTR + khalf;

    uint32_t d[2][8][4];
#pragma unroll
    for (int m = 0; m < 2; ++m)
#pragma unroll
        for (int n = 0; n < 8; ++n)
#pragma unroll
            for (int q = 0; q < 4; ++q) d[m][n][q] = 0u;

    const int NC = K >> 6;

    // stage loader: 512 16B-chunks per operand, 2 per thread each
    const int ldRow = tid >> 2, ldCh = (tid & 3) << 4;    // chunk within thread's pair
    const unsigned char* gA = A + (size_t)(rowBase + ldRow) * K + ldCh;
    const unsigned char* gB = W + (size_t)(colBase + ldRow) * K + ldCh;
    const unsigned char* gA2 = A + (size_t)(rowBase + ldRow + 64) * K + ldCh;
    const unsigned char* gB2 = W + (size_t)(colBase + ldRow + 64) * K + ldCh;
    const uint32_t sA0 = sb + (uint32_t)ldRow * RSTR + ldCh;
    const uint32_t sA1 = sb + (uint32_t)(ldRow + 64) * RSTR + ldCh;
    const uint32_t sB0 = sb + 2 * STAGE + (uint32_t)ldRow * RSTR + ldCh;
    const uint32_t sB1 = sb + 2 * STAGE + (uint32_t)(ldRow + 64) * RSTR + ldCh;

    // prologue: load chunk 0 into stage 0
    cp_async16(sA0, gA);
    cp_async16(sA1, gA2);
    cp_async16(sB0, gB);
    cp_async16(sB1, gB2);
    asm volatile("cp.async.commit_group;" ::: "memory");

    for (int c = 0; c < NC; ++c) {
        if (c + 1 < NC) {
            const uint32_t so = (uint32_t)((c + 1) & 1) * STAGE;
            const int ko = (c + 1) << 6;
            cp_async16(sA0 + so, gA + ko);
            cp_async16(sA1 + so, gA2 + ko);
            cp_async16(sB0 + so, gB + ko);
            cp_async16(sB1 + so, gB2 + ko);
            asm volatile("cp.async.commit_group;" ::: "memory");
            asm volatile("cp.async.wait_group 1;" ::: "memory");
        } else {
            asm volatile("cp.async.wait_group 0;" ::: "memory");
        }
        __syncthreads();

        const uint32_t so = (uint32_t)(c & 1) * STAGE;
#pragma unroll
        for (int ks = 0; ks < 2; ++ks) {
            const uint32_t ko = so + (uint32_t)(ks << 5);
            uint32_t af[2][4], bf[4][4];
#pragma unroll
            for (int m = 0; m < 2; ++m) ldsm_x4(af[m], aBase[m] + ko);
#pragma unroll
            for (int p = 0; p < 4; ++p) ldsm_x4(bf[p], bBase[p] + ko);
#pragma unroll
            for (int m = 0; m < 2; ++m)
#pragma unroll
                for (int n = 0; n < 8; ++n) {
                    const int p = n >> 1, h = n & 1;
                    mma_s8(d[m][n], af[m], bf[p][h], bf[p][h + 2]);
                }
        }
        __syncthreads();
    }

    // Epilogue: BN threshold (bit-matched fp32 ordering), write ±1 s8
    const int row0 = rowBase + warpM * 32 + (lane >> 2);
    const int col0 = colBase + warpN * 64 + ((lane & 3) << 1);
#pragma unroll
    for (int m = 0; m < 2; ++m)
#pragma unroll
        for (int n = 0; n < 8; ++n) {
            const int col = col0 + n * 8;
            const float4 p0 = par[col];
            const float4 p1 = par[col + 1];
#pragma unroll
            for (int rh = 0; rh < 2; ++rh) {
                const int r = row0 + m * 16 + rh * 8;
                float h0 = __fadd_rn((float)(int)d[m][n][rh * 2 + 0], p0.x);
                float h1 = __fadd_rn((float)(int)d[m][n][rh * 2 + 1], p1.x);
                float f0 = __fadd_rn(__fmul_rn(__fsub_rn(h0, p0.y), p0.z), p0.w);
                float f1 = __fadd_rn(__fmul_rn(__fsub_rn(h1, p1.y), p1.z), p1.w);
                uchar2 o;
                o.x = (f0 < 0.f) ? 0xFF : 0x01;
                o.y = (f1 < 0.f) ? 0xFF : 0x01;
                *(uchar2*)(Out + (size_t)r * HID + col) = o;
            }
        }
}

// ---------------------------------------------------------------------------
// Layer 4 (4096 -> 10) via dp4a + BN + log_softmax. One warp per row.
// ---------------------------------------------------------------------------
__global__ void final_kernel(const unsigned char* __restrict__ A, const unsigned char* __restrict__ W4,
                             const float* __restrict__ bias, const float* __restrict__ gam,
                             const float* __restrict__ bet,  const float* __restrict__ mean,
                             const float* __restrict__ var,  float* __restrict__ out) {
    int wg   = (blockIdx.x * blockDim.x + threadIdx.x) >> 5;
    int lane = threadIdx.x & 31;
    if (wg >= NROWS) return;

    const int4* arow = (const int4*)(A + (size_t)wg * HID);
    int4 av[8];
#pragma unroll
    for (int i = 0; i < 8; ++i) av[i] = arow[lane * 8 + i];

    float f[10];
#pragma unroll
    for (int o = 0; o < 10; ++o) {
        const int4* wrow = (const int4*)(W4 + (size_t)o * HID);
        int acc = 0;
#pragma unroll
        for (int i = 0; i < 8; ++i) {
            int4 wv = wrow[lane * 8 + i];
            acc = __dp4a(av[i].x, wv.x, acc);
            acc = __dp4a(av[i].y, wv.y, acc);
            acc = __dp4a(av[i].z, wv.z, acc);
            acc = __dp4a(av[i].w, wv.w, acc);
        }
        int tot = __reduce_add_sync(0xffffffffu, acc);
        float hf    = __fadd_rn((float)tot, bias[o]);
        float scale = __fmul_rn(gam[o], rsqrtf(__fadd_rn(var[o], EPSV)));
        f[o] = __fadd_rn(__fmul_rn(__fsub_rn(hf, mean[o]), scale), bet[o]);
    }
    float mx = f[0];
#pragma unroll
    for (int o = 1; o < 10; ++o) mx = fmaxf(mx, f[o]);
    float s = 0.0f;
#pragma unroll
    for (int o = 0; o < 10; ++o) s += expf(f[o] - mx);
    float lse = logf(s);
    if (lane < 10) out[(size_t)wg * 10 + lane] = (f[lane] - mx) - lse;
}

// ---------------------------------------------------------------------------
extern "C" void kernel_launch(void* const* d_in, const int* in_sizes, int n_in,
                              void* d_out, int out_size) {
    (void)in_sizes; (void)n_in; (void)out_size;
    const float* x  = (const float*)d_in[0];
    const float* w1 = (const float*)d_in[1];
    const float* b1 = (const float*)d_in[2];
    const float* g1 = (const float*)d_in[3];
    const float* be1= (const float*)d_in[4];
    const float* m1 = (const float*)d_in[5];
    const float* v1 = (const float*)d_in[6];
    const float* w2 = (const float*)d_in[7];
    const float* b2 = (const float*)d_in[8];
    const float* g2 = (const float*)d_in[9];
    const float* be2= (const float*)d_in[10];
    const float* m2 = (const float*)d_in[11];
    const float* v2 = (const float*)d_in[12];
    const float* w3 = (const float*)d_in[13];
    const float* b3 = (const float*)d_in[14];
    const float* g3 = (const float*)d_in[15];
    const float* be3= (const float*)d_in[16];
    const float* m3 = (const float*)d_in[17];
    const float* v3 = (const float*)d_in[18];
    const float* w4 = (const float*)d_in[19];
    const float* b4 = (const float*)d_in[20];
    const float* g4 = (const float*)d_in[21];
    const float* be4= (const float*)d_in[22];
    const float* m4 = (const float*)d_in[23];
    const float* v4 = (const float*)d_in[24];
    float* out = (float*)d_out;

    unsigned char *xb, *a0, *a1, *pw1, *pw2, *pw3, *pw4;
    float4* par;
    cudaGetSymbolAddress((void**)&xb,  g_xb);
    cudaGetSymbolAddress((void**)&a0,  g_act0);
    cudaGetSymbolAddress((void**)&a1,  g_act1);
    cudaGetSymbolAddress((void**)&pw1, g_w1);
    cudaGetSymbolAddress((void**)&pw2, g_w2);
    cudaGetSymbolAddress((void**)&pw3, g_w3);
    cudaGetSymbolAddress((void**)&pw4, g_w4);
    cudaGetSymbolAddress((void**)&par, g_par);

    // ±1 s8 conversions
    cvt_sign_x<<<(NROWS * 192 + 255) / 256, 256>>>(x, xb);
    cvt_sign<<<(HID * 768 / 4 + 255) / 256, 256>>>(w1, pw1, HID * 768 / 4);
    cvt_sign<<<(HID * HID / 4 + 255) / 256, 256>>>(w2, pw2, HID * HID / 4);
    cvt_sign<<<(HID * HID / 4 + 255) / 256, 256>>>(w3, pw3, HID * HID / 4);
    cvt_sign<<<(10 * HID / 4 + 255) / 256, 256>>>(w4, pw4, 10 * HID / 4);

    // BN parameter packs
    prep_par<<<16, 256>>>(b1, g1, be1, m1, v1, par,           HID);
    prep_par<<<16, 256>>>(b2, g2, be2, m2, v2, par + HID,     HID);
    prep_par<<<16, 256>>>(b3, g3, be3, m3, v3, par + 2 * HID, HID);

    dim3 grid(HID / 128, NROWS / 128);
    imma_kernel<<<grid, 256>>>(xb, pw1, par,           a0, 768);
    imma_kernel<<<grid, 256>>>(a0, pw2, par + HID,     a1, HID);
    imma_kernel<<<grid, 256>>>(a1, pw3, par + 2 * HID, a0, HID);

    final_kernel<<<(NROWS * 32) / 256, 256>>>(a0, pw4, b4, g4, be4, m4, v4, out);
}

// round 4
// speedup vs baseline: 3.0423x; 3.0423x over previous
#include <cuda_runtime.h>
#include <cstdint>
#include <cstddef>

#define NROWS 16384
#define HID   4096
#define EPSV  1e-5f

// ---------------------------------------------------------------------------
// Scratch (device globals; no allocation allowed)
// ---------------------------------------------------------------------------
__device__ uint32_t g_xb  [NROWS * 24];    // binarized input  [16384][24]
__device__ uint32_t g_act0[NROWS * 128];   // packed activations ping
__device__ uint32_t g_act1[NROWS * 128];   // packed activations pong
__device__ uint32_t g_wb1 [4096 * 24];
__device__ uint32_t g_wb2 [4096 * 128];
__device__ uint32_t g_wb3 [4096 * 128];
__device__ uint32_t g_wb4 [16   * 128];

// ---------------------------------------------------------------------------
// LOP3 helpers: 3-input XOR (0x96) and majority (0xE8)
// ---------------------------------------------------------------------------
__device__ __forceinline__ uint32_t xor3(uint32_t a, uint32_t b, uint32_t c) {
    uint32_t r;
    asm("lop3.b32 %0, %1, %2, %3, 0x96;" : "=r"(r) : "r"(a), "r"(b), "r"(c));
    return r;
}
__device__ __forceinline__ uint32_t maj3(uint32_t a, uint32_t b, uint32_t c) {
    uint32_t r;
    asm("lop3.b32 %0, %1, %2, %3, 0xE8;" : "=r"(r) : "r"(a), "r"(b), "r"(c));
    return r;
}

// ---------------------------------------------------------------------------
// Binarize: bit = (value < 0)  (x>=0 -> +1 matches ste_sign, incl. -0.0)
// ---------------------------------------------------------------------------
__global__ void binarize_kernel(const float* __restrict__ src, uint32_t* __restrict__ dst,
                                int rows, int kwords, int stride) {
    int wg   = (blockIdx.x * blockDim.x + threadIdx.x) >> 5;
    int lane = threadIdx.x & 31;
    if (wg >= rows) return;
    const float* p = src + (size_t)wg * (size_t)stride;
    for (int w = 0; w < kwords; ++w) {
        unsigned bits = __ballot_sync(0xffffffffu, p[w * 32 + lane] < 0.0f);
        if (lane == 0) dst[(size_t)wg * kwords + w] = bits;
    }
}

// ---------------------------------------------------------------------------
// Bit-GEMM (Harley-Seal CSA-8) + BN-threshold + repack.
// Tile: 128 rows x 64 cols per CTA, 256 threads, 8x4 outputs/thread.
// K in chunks of KCH words through shared memory; inner loop consumes k in
// blocks of 8 via carry-save adders: 4 POPC per 8 words instead of 8.
// ---------------------------------------------------------------------------
template<int KW, int KCH>
__global__ void __launch_bounds__(256, 2) bitgemm_kernel(
        const uint32_t* __restrict__ A, const uint32_t* __restrict__ W,
        const float* __restrict__ bias, const float* __restrict__ gam,
        const float* __restrict__ bet,  const float* __restrict__ mean,
        const float* __restrict__ var,  uint32_t* __restrict__ O, int Kfull) {
    __shared__ uint32_t As[128][KCH + 1];
    __shared__ uint32_t Ws[64][KCH + 1];

    const int tid     = threadIdx.x;
    const int rowBase = blockIdx.y * 128;
    const int colBase = blockIdx.x * 64;
    const int tx = tid & 15;   // -> 4 cols
    const int ty = tid >> 4;   // -> 8 rows

    uint32_t acc[8][4];
#pragma unroll
    for (int i = 0; i < 8; ++i)
#pragma unroll
        for (int j = 0; j < 4; ++j) acc[i][j] = 0u;

    for (int kb = 0; kb < KW; kb += KCH) {
        for (int idx = tid; idx < 128 * KCH; idx += 256) {
            int r = idx / KCH, k = idx - r * KCH;
            As[r][k] = A[(size_t)(rowBase + r) * KW + kb + k];
        }
        for (int idx = tid; idx < 64 * KCH; idx += 256) {
            int r = idx / KCH, k = idx - r * KCH;
            Ws[r][k] = W[(size_t)(colBase + r) * KW + kb + k];
        }
        __syncthreads();

#pragma unroll
        for (int k8 = 0; k8 < KCH; k8 += 8) {
            // cache W words for this 8-k block: 4 cols x 8 k
            uint32_t ww[4][8];
#pragma unroll
            for (int j = 0; j < 4; ++j)
#pragma unroll
                for (int k = 0; k < 8; ++k) ww[j][k] = Ws[tx * 4 + j][k8 + k];

#pragma unroll
            for (int i = 0; i < 8; ++i) {
                uint32_t aw[8];
#pragma unroll
                for (int k = 0; k < 8; ++k) aw[k] = As[ty * 8 + i][k8 + k];
#pragma unroll
                for (int j = 0; j < 4; ++j) {
                    uint32_t x0 = aw[0] ^ ww[j][0];
                    uint32_t x1 = aw[1] ^ ww[j][1];
                    uint32_t x2 = aw[2] ^ ww[j][2];
                    uint32_t x3 = aw[3] ^ ww[j][3];
                    uint32_t x4 = aw[4] ^ ww[j][4];
                    uint32_t x5 = aw[5] ^ ww[j][5];
                    uint32_t x6 = aw[6] ^ ww[j][6];
                    uint32_t x7 = aw[7] ^ ww[j][7];
                    // CSA tree: ones(x0..x7) = popc(s3)+popc(x7)+2*popc(s4)+4*popc(c4)
                    uint32_t s1 = xor3(x0, x1, x2), c1 = maj3(x0, x1, x2);
                    uint32_t s2 = xor3(x3, x4, x5), c2 = maj3(x3, x4, x5);
                    uint32_t s3 = xor3(s1, s2, x6), c3 = maj3(s1, s2, x6);
                    uint32_t s4 = xor3(c1, c2, c3), c4 = maj3(c1, c2, c3);
                    uint32_t t  = (uint32_t)__popc(s3) + (uint32_t)__popc(x7);
                    uint32_t u  = (uint32_t)__popc(s4) + ((uint32_t)__popc(c4) << 1);
                    acc[i][j] += t + (u << 1);
                }
            }
        }
        __syncthreads();
    }

    // Epilogue: BN threshold -> flag bytes in (reused) shared memory
    uint8_t* flags = (uint8_t*)&As[0][0];   // 128*64 = 8KB, fits in As
#pragma unroll
    for (int j = 0; j < 4; ++j) {
        int n = colBase + tx * 4 + j;
        float scale = __fmul_rn(gam[n], rsqrtf(__fadd_rn(var[n], EPSV)));
        float mn = mean[n], bt = bet[n], bs = bias[n];
#pragma unroll
        for (int i = 0; i < 8; ++i) {
            float hf = __fadd_rn((float)(Kfull - 2 * (int)acc[i][j]), bs);
            float f  = __fadd_rn(__fmul_rn(__fsub_rn(hf, mn), scale), bt);
            flags[(ty * 8 + i) * 64 + tx * 4 + j] = (f < 0.0f) ? (uint8_t)1 : (uint8_t)0;
        }
    }
    __syncthreads();

    // Pack: 128 rows x 2 output words = 256 words, one per thread
    {
        int r = tid >> 1, cw = tid & 1;
        const uint8_t* fr = flags + r * 64 + cw * 32;
        uint32_t wbits = 0u;
#pragma unroll
        for (int i = 0; i < 32; ++i) wbits |= ((uint32_t)fr[i]) << i;
        O[(size_t)(rowBase + r) * 128 + (colBase >> 5) + cw] = wbits;
    }
}

// ---------------------------------------------------------------------------
// Layer 4 (4096 -> 10) + BN + log_softmax. One warp per row.
// ---------------------------------------------------------------------------
__global__ void final_kernel(const uint32_t* __restrict__ A, const uint32_t* __restrict__ W4,
                             const float* __restrict__ bias, const float* __restrict__ gam,
                             const float* __restrict__ bet,  const float* __restrict__ mean,
                             const float* __restrict__ var,  float* __restrict__ out) {
    int wg   = (blockIdx.x * blockDim.x + threadIdx.x) >> 5;
    int lane = threadIdx.x & 31;
    if (wg >= NROWS) return;

    uint32_t aw[4];
#pragma unroll
    for (int j = 0; j < 4; ++j) aw[j] = A[(size_t)wg * 128 + j * 32 + lane];

    float f[10];
#pragma unroll
    for (int o = 0; o < 10; ++o) {
        uint32_t c = 0u;
#pragma unroll
        for (int j = 0; j < 4; ++j) c += (uint32_t)__popc(aw[j] ^ W4[o * 128 + j * 32 + lane]);
        uint32_t tot = __reduce_add_sync(0xffffffffu, c);
        float hf    = __fadd_rn((float)(4096 - 2 * (int)tot), bias[o]);
        float scale = __fmul_rn(gam[o], rsqrtf(__fadd_rn(var[o], EPSV)));
        f[o] = __fadd_rn(__fmul_rn(__fsub_rn(hf, mean[o]), scale), bet[o]);
    }
    float mx = f[0];
#pragma unroll
    for (int o = 1; o < 10; ++o) mx = fmaxf(mx, f[o]);
    float s = 0.0f;
#pragma unroll
    for (int o = 0; o < 10; ++o) s += expf(f[o] - mx);
    float lse = logf(s);
    if (lane < 10) out[(size_t)wg * 10 + lane] = (f[lane] - mx) - lse;
}

// ---------------------------------------------------------------------------
extern "C" void kernel_launch(void* const* d_in, const int* in_sizes, int n_in,
                              void* d_out, int out_size) {
    (void)in_sizes; (void)n_in; (void)out_size;
    const float* x  = (const float*)d_in[0];
    const float* w1 = (const float*)d_in[1];
    const float* b1 = (const float*)d_in[2];
    const float* g1 = (const float*)d_in[3];
    const float* be1= (const float*)d_in[4];
    const float* m1 = (const float*)d_in[5];
    const float* v1 = (const float*)d_in[6];
    const float* w2 = (const float*)d_in[7];
    const float* b2 = (const float*)d_in[8];
    const float* g2 = (const float*)d_in[9];
    const float* be2= (const float*)d_in[10];
    const float* m2 = (const float*)d_in[11];
    const float* v2 = (const float*)d_in[12];
    const float* w3 = (const float*)d_in[13];
    const float* b3 = (const float*)d_in[14];
    const float* g3 = (const float*)d_in[15];
    const float* be3= (const float*)d_in[16];
    const float* m3 = (const float*)d_in[17];
    const float* v3 = (const float*)d_in[18];
    const float* w4 = (const float*)d_in[19];
    const float* b4 = (const float*)d_in[20];
    const float* g4 = (const float*)d_in[21];
    const float* be4= (const float*)d_in[22];
    const float* m4 = (const float*)d_in[23];
    const float* v4 = (const float*)d_in[24];
    float* out = (float*)d_out;

    uint32_t *xb, *a0, *a1, *wb1, *wb2, *wb3, *wb4;
    cudaGetSymbolAddress((void**)&xb,  g_xb);
    cudaGetSymbolAddress((void**)&a0,  g_act0);
    cudaGetSymbolAddress((void**)&a1,  g_act1);
    cudaGetSymbolAddress((void**)&wb1, g_wb1);
    cudaGetSymbolAddress((void**)&wb2, g_wb2);
    cudaGetSymbolAddress((void**)&wb3, g_wb3);
    cudaGetSymbolAddress((void**)&wb4, g_wb4);

    // Binarize input + weights (bit = value<0)
    binarize_kernel<<<(NROWS * 32) / 256, 256>>>(x,  xb,  NROWS, 24, 784);
    binarize_kernel<<<(4096  * 32) / 256, 256>>>(w1, wb1, 4096, 24, 768);
    binarize_kernel<<<(4096  * 32) / 256, 256>>>(w2, wb2, 4096, 128, 4096);
    binarize_kernel<<<(4096  * 32) / 256, 256>>>(w3, wb3, 4096, 128, 4096);
    binarize_kernel<<<2, 256>>>(w4, wb4, 10, 128, 4096);

    dim3 grid(4096 / 64, NROWS / 128);
    // L1: K=768 (24 words, 3 CSA-8 blocks per chunk)
    bitgemm_kernel<24, 24><<<grid, 256>>>(xb, wb1, b1, g1, be1, m1, v1, a0, 768);
    // L2/L3: K=4096 (128 words, chunks of 32 = 4 CSA-8 blocks)
    bitgemm_kernel<128, 32><<<grid, 256>>>(a0, wb2, b2, g2, be2, m2, v2, a1, 4096);
    bitgemm_kernel<128, 32><<<grid, 256>>>(a1, wb3, b3, g3, be3, m3, v3, a0, 4096);
    // L4 + log_softmax
    final_kernel<<<(NROWS * 32) / 256, 256>>>(a0, wb4, b4, g4, be4, m4, v4, out);
}

// round 7
// speedup vs baseline: 3.0876x; 1.0149x over previous
#include <cuda_runtime.h>
#include <cstdint>
#include <cstddef>

#define NROWS 16384
#define HID   4096
#define EPSV  1e-5f

// ---------------------------------------------------------------------------
// Scratch (device globals; no allocation allowed)
// ---------------------------------------------------------------------------
__device__ uint32_t g_xb  [NROWS * 24];    // binarized input  [16384][24]
__device__ uint32_t g_act0[NROWS * 128];   // packed activations ping
__device__ uint32_t g_act1[NROWS * 128];   // packed activations pong
__device__ uint32_t g_wb1 [4096 * 24];
__device__ uint32_t g_wb2 [4096 * 128];
__device__ uint32_t g_wb3 [4096 * 128];
__device__ uint32_t g_wb4 [16   * 128];

// ---------------------------------------------------------------------------
// LOP3 helpers: 3-input XOR (0x96) and majority (0xE8)   [alu pipe]
// IMAD accumulate with runtime multiplier                [fma pipe]
// ---------------------------------------------------------------------------
__device__ __forceinline__ uint32_t xor3(uint32_t a, uint32_t b, uint32_t c) {
    uint32_t r;
    asm("lop3.b32 %0, %1, %2, %3, 0x96;" : "=r"(r) : "r"(a), "r"(b), "r"(c));
    return r;
}
__device__ __forceinline__ uint32_t maj3(uint32_t a, uint32_t b, uint32_t c) {
    uint32_t r;
    asm("lop3.b32 %0, %1, %2, %3, 0xE8;" : "=r"(r) : "r"(a), "r"(b), "r"(c));
    return r;
}
__device__ __forceinline__ void imad_acc(uint32_t& acc, uint32_t p, uint32_t w) {
    asm("mad.lo.u32 %0, %1, %2, %0;" : "+r"(acc) : "r"(p), "r"(w));
}

// ---------------------------------------------------------------------------
// Binarize: bit = (value < 0)  (x>=0 -> +1 matches ste_sign, incl. -0.0)
// ---------------------------------------------------------------------------
__global__ void binarize_kernel(const float* __restrict__ src, uint32_t* __restrict__ dst,
                                int rows, int kwords, int stride) {
    int wg   = (blockIdx.x * blockDim.x + threadIdx.x) >> 5;
    int lane = threadIdx.x & 31;
    if (wg >= rows) return;
    const float* p = src + (size_t)wg * (size_t)stride;
    for (int w = 0; w < kwords; ++w) {
        unsigned bits = __ballot_sync(0xffffffffu, p[w * 32 + lane] < 0.0f);
        if (lane == 0) dst[(size_t)wg * kwords + w] = bits;
    }
}

// ---------------------------------------------------------------------------
// Bit-GEMM (Harley-Seal CSA-8) + BN-threshold + repack.
// Tile: 128 rows x 64 cols per CTA, 256 threads, 8x4 outputs/thread.
// ALU pipe carries only XOR + LOP3 (2 ops/word floor); popc accumulation is
// routed to the FMA pipe via IMAD with runtime multipliers (oneArg=1).
// ---------------------------------------------------------------------------
template<int KW, int KCH>
__global__ void __launch_bounds__(256, 2) bitgemm_kernel(
        const uint32_t* __restrict__ A, const uint32_t* __restrict__ W,
        const float* __restrict__ bias, const float* __restrict__ gam,
        const float* __restrict__ bet,  const float* __restrict__ mean,
        const float* __restrict__ var,  uint32_t* __restrict__ O, int Kfull,
        uint32_t oneArg) {
    __shared__ uint32_t As[128][KCH + 1];
    __shared__ uint32_t Ws[64][KCH + 1];

    const int tid     = threadIdx.x;
    const int rowBase = blockIdx.y * 128;
    const int colBase = blockIdx.x * 64;
    const int tx = tid & 15;   // -> 4 cols
    const int ty = tid >> 4;   // -> 8 rows

    const uint32_t w1m = oneArg;           // 1 (opaque to ptxas)
    const uint32_t w2m = oneArg + oneArg;  // 2
    const uint32_t w4m = w2m + w2m;        // 4

    uint32_t acc[8][4];
#pragma unroll
    for (int i = 0; i < 8; ++i)
#pragma unroll
        for (int j = 0; j < 4; ++j) acc[i][j] = 0u;

    for (int kb = 0; kb < KW; kb += KCH) {
        for (int idx = tid; idx < 128 * KCH; idx += 256) {
            int r = idx / KCH, k = idx - r * KCH;
            As[r][k] = A[(size_t)(rowBase + r) * KW + kb + k];
        }
        for (int idx = tid; idx < 64 * KCH; idx += 256) {
            int r = idx / KCH, k = idx - r * KCH;
            Ws[r][k] = W[(size_t)(colBase + r) * KW + kb + k];
        }
        __syncthreads();

#pragma unroll
        for (int k8 = 0; k8 < KCH; k8 += 8) {
            // cache W words for this 8-k block: 4 cols x 8 k
            uint32_t ww[4][8];
#pragma unroll
            for (int j = 0; j < 4; ++j)
#pragma unroll
                for (int k = 0; k < 8; ++k) ww[j][k] = Ws[tx * 4 + j][k8 + k];

#pragma unroll
            for (int i = 0; i < 8; ++i) {
                uint32_t aw[8];
#pragma unroll
                for (int k = 0; k < 8; ++k) aw[k] = As[ty * 8 + i][k8 + k];
#pragma unroll
                for (int j = 0; j < 4; ++j) {
                    uint32_t x0 = aw[0] ^ ww[j][0];
                    uint32_t x1 = aw[1] ^ ww[j][1];
                    uint32_t x2 = aw[2] ^ ww[j][2];
                    uint32_t x3 = aw[3] ^ ww[j][3];
                    uint32_t x4 = aw[4] ^ ww[j][4];
                    uint32_t x5 = aw[5] ^ ww[j][5];
                    uint32_t x6 = aw[6] ^ ww[j][6];
                    uint32_t x7 = aw[7] ^ ww[j][7];
                    // CSA tree: ones(x0..x7) = popc(s3)+popc(x7)+2*popc(s4)+4*popc(c4)
                    uint32_t s1 = xor3(x0, x1, x2), c1 = maj3(x0, x1, x2);
                    uint32_t s2 = xor3(x3, x4, x5), c2 = maj3(x3, x4, x5);
                    uint32_t s3 = xor3(s1, s2, x6), c3 = maj3(s1, s2, x6);
                    uint32_t s4 = xor3(c1, c2, c3), c4 = maj3(c1, c2, c3);
                    uint32_t p1 = (uint32_t)__popc(s3);
                    uint32_t p2 = (uint32_t)__popc(x7);
                    uint32_t p3 = (uint32_t)__popc(s4);
                    uint32_t p4 = (uint32_t)__popc(c4);
                    imad_acc(acc[i][j], p1, w1m);   // fma pipe
                    imad_acc(acc[i][j], p2, w1m);   // fma pipe
                    imad_acc(acc[i][j], p3, w2m);   // fma pipe
                    imad_acc(acc[i][j], p4, w4m);   // fma pipe
                }
            }
        }
        __syncthreads();
    }

    // Epilogue: BN threshold -> flag bytes in (reused) shared memory
    uint8_t* flags = (uint8_t*)&As[0][0];   // 128*64 = 8KB, fits in As
#pragma unroll
    for (int j = 0; j < 4; ++j) {
        int n = colBase + tx * 4 + j;
        float scale = __fmul_rn(gam[n], rsqrtf(__fadd_rn(var[n], EPSV)));
        float mn = mean[n], bt = bet[n], bs = bias[n];
#pragma unroll
        for (int i = 0; i < 8; ++i) {
            float hf = __fadd_rn((float)(Kfull - 2 * (int)acc[i][j]), bs);
            float f  = __fadd_rn(__fmul_rn(__fsub_rn(hf, mn), scale), bt);
            flags[(ty * 8 + i) * 64 + tx * 4 + j] = (f < 0.0f) ? (uint8_t)1 : (uint8_t)0;
        }
    }
    __syncthreads();

    // Pack: 128 rows x 2 output words = 256 words, one per thread
    {
        int r = tid >> 1, cw = tid & 1;
        const uint8_t* fr = flags + r * 64 + cw * 32;
        uint32_t wbits = 0u;
#pragma unroll
        for (int i = 0; i < 32; ++i) wbits |= ((uint32_t)fr[i]) << i;
        O[(size_t)(rowBase + r) * 128 + (colBase >> 5) + cw] = wbits;
    }
}

// ---------------------------------------------------------------------------
// Layer 4 (4096 -> 10) + BN + log_softmax. One warp per row.
// ---------------------------------------------------------------------------
__global__ void final_kernel(const uint32_t* __restrict__ A, const uint32_t* __restrict__ W4,
                             const float* __restrict__ bias, const float* __restrict__ gam,
                             const float* __restrict__ bet,  const float* __restrict__ mean,
                             const float* __restrict__ var,  float* __restrict__ out) {
    int wg   = (blockIdx.x * blockDim.x + threadIdx.x) >> 5;
    int lane = threadIdx.x & 31;
    if (wg >= NROWS) return;

    uint32_t aw[4];
#pragma unroll
    for (int j = 0; j < 4; ++j) aw[j] = A[(size_t)wg * 128 + j * 32 + lane];

    float f[10];
#pragma unroll
    for (int o = 0; o < 10; ++o) {
        uint32_t c = 0u;
#pragma unroll
        for (int j = 0; j < 4; ++j) c += (uint32_t)__popc(aw[j] ^ W4[o * 128 + j * 32 + lane]);
        uint32_t tot = __reduce_add_sync(0xffffffffu, c);
        float hf    = __fadd_rn((float)(4096 - 2 * (int)tot), bias[o]);
        float scale = __fmul_rn(gam[o], rsqrtf(__fadd_rn(var[o], EPSV)));
        f[o] = __fadd_rn(__fmul_rn(__fsub_rn(hf, mean[o]), scale), bet[o]);
    }
    float mx = f[0];
#pragma unroll
    for (int o = 1; o < 10; ++o) mx = fmaxf(mx, f[o]);
    float s = 0.0f;
#pragma unroll
    for (int o = 0; o < 10; ++o) s += expf(f[o] - mx);
    float lse = logf(s);
    if (lane < 10) out[(size_t)wg * 10 + lane] = (f[lane] - mx) - lse;
}

// ---------------------------------------------------------------------------
extern "C" void kernel_launch(void* const* d_in, const int* in_sizes, int n_in,
                              void* d_out, int out_size) {
    (void)in_sizes; (void)n_in; (void)out_size;
    const float* x  = (const float*)d_in[0];
    const float* w1 = (const float*)d_in[1];
    const float* b1 = (const float*)d_in[2];
    const float* g1 = (const float*)d_in[3];
    const float* be1= (const float*)d_in[4];
    const float* m1 = (const float*)d_in[5];
    const float* v1 = (const float*)d_in[6];
    const float* w2 = (const float*)d_in[7];
    const float* b2 = (const float*)d_in[8];
    const float* g2 = (const float*)d_in[9];
    const float* be2= (const float*)d_in[10];
    const float* m2 = (const float*)d_in[11];
    const float* v2 = (const float*)d_in[12];
    const float* w3 = (const float*)d_in[13];
    const float* b3 = (const float*)d_in[14];
    const float* g3 = (const float*)d_in[15];
    const float* be3= (const float*)d_in[16];
    const float* m3 = (const float*)d_in[17];
    const float* v3 = (const float*)d_in[18];
    const float* w4 = (const float*)d_in[19];
    const float* b4 = (const float*)d_in[20];
    const float* g4 = (const float*)d_in[21];
    const float* be4= (const float*)d_in[22];
    const float* m4 = (const float*)d_in[23];
    const float* v4 = (const float*)d_in[24];
    float* out = (float*)d_out;

    uint32_t *xb, *a0, *a1, *wb1, *wb2, *wb3, *wb4;
    cudaGetSymbolAddress((void**)&xb,  g_xb);
    cudaGetSymbolAddress((void**)&a0,  g_act0);
    cudaGetSymbolAddress((void**)&a1,  g_act1);
    cudaGetSymbolAddress((void**)&wb1, g_wb1);
    cudaGetSymbolAddress((void**)&wb2, g_wb2);
    cudaGetSymbolAddress((void**)&wb3, g_wb3);
    cudaGetSymbolAddress((void**)&wb4, g_wb4);

    // Binarize input + weights (bit = value<0)
    binarize_kernel<<<(NROWS * 32) / 256, 256>>>(x,  xb,  NROWS, 24, 784);
    binarize_kernel<<<(4096  * 32) / 256, 256>>>(w1, wb1, 4096, 24, 768);
    binarize_kernel<<<(4096  * 32) / 256, 256>>>(w2, wb2, 4096, 128, 4096);
    binarize_kernel<<<(4096  * 32) / 256, 256>>>(w3, wb3, 4096, 128, 4096);
    binarize_kernel<<<2, 256>>>(w4, wb4, 10, 128, 4096);

    dim3 grid(4096 / 64, NROWS / 128);
    // L1: K=768 (24 words, 3 CSA-8 blocks per chunk)
    bitgemm_kernel<24, 24><<<grid, 256>>>(xb, wb1, b1, g1, be1, m1, v1, a0, 768, 1u);
    // L2/L3: K=4096 (128 words, chunks of 32 = 4 CSA-8 blocks)
    bitgemm_kernel<128, 32><<<grid, 256>>>(a0, wb2, b2, g2, be2, m2, v2, a1, 4096, 1u);
    bitgemm_kernel<128, 32><<<grid, 256>>>(a1, wb3, b3, g3, be3, m3, v3, a0, 4096, 1u);
    // L4 + log_softmax
    final_kernel<<<(NROWS * 32) / 256, 256>>>(a0, wb4, b4, g4, be4, m4, v4, out);
}

// round 8
// speedup vs baseline: 3.3193x; 1.0750x over previous
#include <cuda_runtime.h>
#include <cstdint>
#include <cstddef>

#define NROWS 16384
#define HID   4096
#define EPSV  1e-5f

// ---------------------------------------------------------------------------
// Scratch (device globals; no allocation allowed)
// ---------------------------------------------------------------------------
__device__ __align__(16) uint32_t g_xb  [NROWS * 24];    // binarized input, row-major [16384][24]
__device__ __align__(16) uint32_t g_act0[NROWS * 128];   // packed activations ping (row-major)
__device__ __align__(16) uint32_t g_act1[NROWS * 128];   // packed activations pong
__device__ __align__(16) uint32_t g_wb1 [24  * 4096];    // W1 binarized K-MAJOR [24][4096]
__device__ __align__(16) uint32_t g_wb2 [128 * 4096];    // W2 K-major [128][4096]
__device__ __align__(16) uint32_t g_wb3 [128 * 4096];    // W3 K-major [128][4096]
__device__ __align__(16) uint32_t g_wb4 [16  * 128];     // W4 row-major [10][128]

// ---------------------------------------------------------------------------
// LOP3 helpers (alu pipe) + IMAD accumulate (fma pipe) + cp.async
// ---------------------------------------------------------------------------
__device__ __forceinline__ uint32_t xor3(uint32_t a, uint32_t b, uint32_t c) {
    uint32_t r;
    asm("lop3.b32 %0, %1, %2, %3, 0x96;" : "=r"(r) : "r"(a), "r"(b), "r"(c));
    return r;
}
__device__ __forceinline__ uint32_t maj3(uint32_t a, uint32_t b, uint32_t c) {
    uint32_t r;
    asm("lop3.b32 %0, %1, %2, %3, 0xE8;" : "=r"(r) : "r"(a), "r"(b), "r"(c));
    return r;
}
__device__ __forceinline__ void imad_acc(uint32_t& acc, uint32_t p, uint32_t w) {
    asm("mad.lo.u32 %0, %1, %2, %0;" : "+r"(acc) : "r"(p), "r"(w));
}
__device__ __forceinline__ uint32_t smem_u32(const void* p) {
    uint32_t a;
    asm("{ .reg .u64 t; cvta.to.shared.u64 t, %1; cvt.u32.u64 %0, t; }" : "=r"(a) : "l"(p));
    return a;
}
__device__ __forceinline__ void cp_async16(uint32_t dst, const void* src) {
    asm volatile("cp.async.cg.shared.global [%0], [%1], 16;" :: "r"(dst), "l"(src) : "memory");
}
#define CP_COMMIT() asm volatile("cp.async.commit_group;" ::: "memory")
#define CP_WAIT0()  asm volatile("cp.async.wait_group 0;" ::: "memory")

// ---------------------------------------------------------------------------
// Binarize row-major: dst[row][w]  (bit = x<0; x>=0 -> +1 incl. -0.0)
// ---------------------------------------------------------------------------
__global__ void binarize_kernel(const float* __restrict__ src, uint32_t* __restrict__ dst,
                                int rows, int kwords, int stride) {
    int wg   = (blockIdx.x * blockDim.x + threadIdx.x) >> 5;
    int lane = threadIdx.x & 31;
    if (wg >= rows) return;
    const float* p = src + (size_t)wg * (size_t)stride;
    for (int w = 0; w < kwords; ++w) {
        unsigned bits = __ballot_sync(0xffffffffu, p[w * 32 + lane] < 0.0f);
        if (lane == 0) dst[(size_t)wg * kwords + w] = bits;
    }
}
// Binarize K-major (transposed): dst[w][row]
__global__ void binarize_T_kernel(const float* __restrict__ src, uint32_t* __restrict__ dst,
                                  int rows, int kwords, int stride, int ncols) {
    int wg   = (blockIdx.x * blockDim.x + threadIdx.x) >> 5;
    int lane = threadIdx.x & 31;
    if (wg >= rows) return;
    const float* p = src + (size_t)wg * (size_t)stride;
    for (int w = 0; w < kwords; ++w) {
        unsigned bits = __ballot_sync(0xffffffffu, p[w * 32 + lane] < 0.0f);
        if (lane == 0) dst[(size_t)w * ncols + wg] = bits;
    }
}

// ---------------------------------------------------------------------------
// Bit-GEMM (CSA-8) + BN-threshold + repack, cp.async double-buffered.
// CTA tile 128 rows x 64 cols, 256 threads, 8x4 outputs/thread.
// A row-major in smem (stride KCH words); W K-major in smem (stride 64 words)
// so ww fetch is one LDS.128 per k (4 j-columns at once).
// ---------------------------------------------------------------------------
template<int KW, int KCH>
__global__ void __launch_bounds__(256, 2) bitgemm_kernel(
        const uint32_t* __restrict__ A,   // row-major [*, KW]
        const uint32_t* __restrict__ Wt,  // K-major  [KW][4096]
        const float* __restrict__ bias, const float* __restrict__ gam,
        const float* __restrict__ bet,  const float* __restrict__ mean,
        const float* __restrict__ var,  uint32_t* __restrict__ O, int Kfull,
        uint32_t oneArg) {
    constexpr int A_BYTES = 128 * KCH * 4;          // A stage bytes
    constexpr int W_BYTES = KCH * 64 * 4;           // W stage bytes
    constexpr int STAGE   = A_BYTES + W_BYTES;
    __shared__ __align__(16) unsigned char smem[2 * STAGE];
    const uint32_t sb = smem_u32(smem);

    const int tid     = threadIdx.x;
    const int rowBase = blockIdx.y * 128;
    const int colBase = blockIdx.x * 64;
    const int tx = tid & 15;   // -> 4 cols (contiguous in K-major W)
    const int ty = tid >> 4;   // -> 8 rows

    const uint32_t w1m = oneArg;           // 1 (opaque to ptxas)
    const uint32_t w2m = oneArg + oneArg;  // 2
    const uint32_t w4m = w2m + w2m;        // 4

    uint32_t acc[8][4];
#pragma unroll
    for (int i = 0; i < 8; ++i)
#pragma unroll
        for (int j = 0; j < 4; ++j) acc[i][j] = 0u;

    constexpr int NA = 128 * (KCH / 4);             // A 16B-chunks per stage
    constexpr int NW = KCH * 16;                    // W 16B-chunks per stage
    constexpr int NC = KW / KCH;

    // chunk loader (cp.async): stage s, k-offset kb
    auto load_chunk = [&](int s, int kb) {
        const uint32_t base = sb + (uint32_t)s * STAGE;
#pragma unroll 2
        for (int idx = tid; idx < NA + NW; idx += 256) {
            if (idx < NA) {
                int r = idx / (KCH / 4), g = idx - r * (KCH / 4);
                cp_async16(base + (uint32_t)(r * KCH + g * 4) * 4,
                           A + (size_t)(rowBase + r) * KW + kb + g * 4);
            } else {
                int idx2 = idx - NA;
                int k = idx2 >> 4, g = idx2 & 15;
                cp_async16(base + A_BYTES + (uint32_t)(k * 64 + g * 4) * 4,
                           Wt + (size_t)(kb + k) * 4096 + colBase + g * 4);
            }
        }
        CP_COMMIT();
    };

    load_chunk(0, 0);

    for (int c = 0; c < NC; ++c) {
        CP_WAIT0();
        __syncthreads();
        if (c + 1 < NC) load_chunk((c + 1) & 1, (c + 1) * KCH);

        const unsigned char* sA = smem + (c & 1) * STAGE;
        const unsigned char* sW = sA + A_BYTES;

#pragma unroll
        for (int k8 = 0; k8 < KCH; k8 += 8) {
            // W: 8 LDS.128 -> ww[j][k] for 4 contiguous cols
            uint4 w8[8];
#pragma unroll
            for (int k = 0; k < 8; ++k)
                w8[k] = *(const uint4*)(sW + (size_t)(k8 + k) * 256 + tx * 16);

#pragma unroll
            for (int i = 0; i < 8; ++i) {
                const unsigned char* ar = sA + (size_t)(ty * 8 + i) * (KCH * 4) + k8 * 4;
                uint4 alo = *(const uint4*)(ar);
                uint4 ahi = *(const uint4*)(ar + 16);
                uint32_t aw[8] = {alo.x, alo.y, alo.z, alo.w, ahi.x, ahi.y, ahi.z, ahi.w};
#pragma unroll
                for (int j = 0; j < 4; ++j) {
                    const uint32_t* wp0 = (const uint32_t*)&w8[0];
                    uint32_t x0 = aw[0] ^ ((const uint32_t*)&w8[0])[j];
                    uint32_t x1 = aw[1] ^ ((const uint32_t*)&w8[1])[j];
                    uint32_t x2 = aw[2] ^ ((const uint32_t*)&w8[2])[j];
                    uint32_t x3 = aw[3] ^ ((const uint32_t*)&w8[3])[j];
                    uint32_t x4 = aw[4] ^ ((const uint32_t*)&w8[4])[j];
                    uint32_t x5 = aw[5] ^ ((const uint32_t*)&w8[5])[j];
                    uint32_t x6 = aw[6] ^ ((const uint32_t*)&w8[6])[j];
                    uint32_t x7 = aw[7] ^ ((const uint32_t*)&w8[7])[j];
                    (void)wp0;
                    // CSA-8: ones = popc(s3)+popc(x7)+2*popc(s4)+4*popc(c4)
                    uint32_t s1 = xor3(x0, x1, x2), c1 = maj3(x0, x1, x2);
                    uint32_t s2 = xor3(x3, x4, x5), c2 = maj3(x3, x4, x5);
                    uint32_t s3 = xor3(s1, s2, x6), c3 = maj3(s1, s2, x6);
                    uint32_t s4 = xor3(c1, c2, c3), c4 = maj3(c1, c2, c3);
                    uint32_t p1 = (uint32_t)__popc(s3);
                    uint32_t p2 = (uint32_t)__popc(x7);
                    uint32_t p3 = (uint32_t)__popc(s4);
                    uint32_t p4 = (uint32_t)__popc(c4);
                    imad_acc(acc[i][j], p1, w1m);   // fma pipe
                    imad_acc(acc[i][j], p2, w1m);
                    imad_acc(acc[i][j], p3, w2m);
                    imad_acc(acc[i][j], p4, w4m);
                }
            }
        }
    }
    __syncthreads();

    // Epilogue: BN threshold -> flag bytes in (reused) shared memory
    uint8_t* flags = (uint8_t*)smem;   // 8KB needed, fits
#pragma unroll
    for (int j = 0; j < 4; ++j) {
        int n = colBase + tx * 4 + j;
        float scale = __fmul_rn(gam[n], rsqrtf(__fadd_rn(var[n], EPSV)));
        float mn = mean[n], bt = bet[n], bs = bias[n];
#pragma unroll
        for (int i = 0; i < 8; ++i) {
            float hf = __fadd_rn((float)(Kfull - 2 * (int)acc[i][j]), bs);
            float f  = __fadd_rn(__fmul_rn(__fsub_rn(hf, mn), scale), bt);
            flags[(ty * 8 + i) * 64 + tx * 4 + j] = (f < 0.0f) ? (uint8_t)1 : (uint8_t)0;
        }
    }
    __syncthreads();

    // Pack: 128 rows x 2 output words = 256 words, one per thread (row-major out)
    {
        int r = tid >> 1, cw = tid & 1;
        const uint8_t* fr = flags + r * 64 + cw * 32;
        uint32_t wbits = 0u;
#pragma unroll
        for (int i = 0; i < 32; ++i) wbits |= ((uint32_t)fr[i]) << i;
        O[(size_t)(rowBase + r) * 128 + (colBase >> 5) + cw] = wbits;
    }
}

// ---------------------------------------------------------------------------
// Layer 4 (4096 -> 10) + BN + log_softmax. One warp per row. (row-major A)
// ---------------------------------------------------------------------------
__global__ void final_kernel(const uint32_t* __restrict__ A, const uint32_t* __restrict__ W4,
                             const float* __restrict__ bias, const float* __restrict__ gam,
                             const float* __restrict__ bet,  const float* __restrict__ mean,
                             const float* __restrict__ var,  float* __restrict__ out) {
    int wg   = (blockIdx.x * blockDim.x + threadIdx.x) >> 5;
    int lane = threadIdx.x & 31;
    if (wg >= NROWS) return;

    uint32_t aw[4];
#pragma unroll
    for (int j = 0; j < 4; ++j) aw[j] = A[(size_t)wg * 128 + j * 32 + lane];

    float f[10];
#pragma unroll
    for (int o = 0; o < 10; ++o) {
        uint32_t c = 0u;
#pragma unroll
        for (int j = 0; j < 4; ++j) c += (uint32_t)__popc(aw[j] ^ W4[o * 128 + j * 32 + lane]);
        uint32_t tot = __reduce_add_sync(0xffffffffu, c);
        float hf    = __fadd_rn((float)(4096 - 2 * (int)tot), bias[o]);
        float scale = __fmul_rn(gam[o], rsqrtf(__fadd_rn(var[o], EPSV)));
        f[o] = __fadd_rn(__fmul_rn(__fsub_rn(hf, mean[o]), scale), bet[o]);
    }
    float mx = f[0];
#pragma unroll
    for (int o = 1; o < 10; ++o) mx = fmaxf(mx, f[o]);
    float s = 0.0f;
#pragma unroll
    for (int o = 0; o < 10; ++o) s += expf(f[o] - mx);
    float lse = logf(s);
    if (lane < 10) out[(size_t)wg * 10 + lane] = (f[lane] - mx) - lse;
}

// ---------------------------------------------------------------------------
extern "C" void kernel_launch(void* const* d_in, const int* in_sizes, int n_in,
                              void* d_out, int out_size) {
    (void)in_sizes; (void)n_in; (void)out_size;
    const float* x  = (const float*)d_in[0];
    const float* w1 = (const float*)d_in[1];
    const float* b1 = (const float*)d_in[2];
    const float* g1 = (const float*)d_in[3];
    const float* be1= (const float*)d_in[4];
    const float* m1 = (const float*)d_in[5];
    const float* v1 = (const float*)d_in[6];
    const float* w2 = (const float*)d_in[7];
    const float* b2 = (const float*)d_in[8];
    const float* g2 = (const float*)d_in[9];
    const float* be2= (const float*)d_in[10];
    const float* m2 = (const float*)d_in[11];
    const float* v2 = (const float*)d_in[12];
    const float* w3 = (const float*)d_in[13];
    const float* b3 = (const float*)d_in[14];
    const float* g3 = (const float*)d_in[15];
    const float* be3= (const float*)d_in[16];
    const float* m3 = (const float*)d_in[17];
    const float* v3 = (const float*)d_in[18];
    const float* w4 = (const float*)d_in[19];
    const float* b4 = (const float*)d_in[20];
    const float* g4 = (const float*)d_in[21];
    const float* be4= (const float*)d_in[22];
    const float* m4 = (const float*)d_in[23];
    const float* v4 = (const float*)d_in[24];
    float* out = (float*)d_out;

    uint32_t *xb, *a0, *a1, *wb1, *wb2, *wb3, *wb4;
    cudaGetSymbolAddress((void**)&xb,  g_xb);
    cudaGetSymbolAddress((void**)&a0,  g_act0);
    cudaGetSymbolAddress((void**)&a1,  g_act1);
    cudaGetSymbolAddress((void**)&wb1, g_wb1);
    cudaGetSymbolAddress((void**)&wb2, g_wb2);
    cudaGetSymbolAddress((void**)&wb3, g_wb3);
    cudaGetSymbolAddress((void**)&wb4, g_wb4);

    // Binarize: x row-major; W1..W3 K-major (transposed); W4 row-major
    binarize_kernel  <<<(NROWS * 32) / 256, 256>>>(x,  xb,  NROWS, 24, 784);
    binarize_T_kernel<<<(4096  * 32) / 256, 256>>>(w1, wb1, 4096, 24, 768, 4096);
    binarize_T_kernel<<<(4096  * 32) / 256, 256>>>(w2, wb2, 4096, 128, 4096, 4096);
    binarize_T_kernel<<<(4096  * 32) / 256, 256>>>(w3, wb3, 4096, 128, 4096, 4096);
    binarize_kernel  <<<2, 256>>>(w4, wb4, 10, 128, 4096);

    dim3 grid(4096 / 64, NROWS / 128);
    // L1: K=768 (24 words, single chunk)
    bitgemm_kernel<24, 24><<<grid, 256>>>(xb, wb1, b1, g1, be1, m1, v1, a0, 768, 1u);
    // L2/L3: K=4096 (128 words, 4 chunks of 32, double-buffered)
    bitgemm_kernel<128, 32><<<grid, 256>>>(a0, wb2, b2, g2, be2, m2, v2, a1, 4096, 1u);
    bitgemm_kernel<128, 32><<<grid, 256>>>(a1, wb3, b3, g3, be3, m3, v3, a0, 4096, 1u);
    // L4 + log_softmax
    final_kernel<<<(NROWS * 32) / 256, 256>>>(a0, wb4, b4, g4, be4, m4, v4, out);
}